// round 3
// baseline (speedup 1.0000x reference)
#include <cuda_runtime.h>
#include <cstdint>

#define BATCH   4
#define NSEQ    2048
#define DMODEL  1024
#define KDIM    32
#define ROWS    (BATCH * NSEQ)
#define CLAMP_V 10.0f

// Scratch: G stored K-MAJOR (g_Gt[k][row]) + per-row squared norms.
__device__ float g_Gt[(size_t)KDIM * ROWS];
__device__ float g_Gsq[ROWS];

// ---- packed f32x2 helpers ---------------------------------------------------
__device__ __forceinline__ unsigned long long pk2(float a, float b) {
    unsigned long long r;
    asm("mov.b64 %0, {%1, %2};" : "=l"(r) : "f"(a), "f"(b));
    return r;
}
__device__ __forceinline__ void unpk2(unsigned long long v, float& a, float& b) {
    asm("mov.b64 {%0, %1}, %2;" : "=f"(a), "=f"(b) : "l"(v));
}
__device__ __forceinline__ unsigned long long fma2(
    unsigned long long a, unsigned long long b, unsigned long long c) {
    unsigned long long d;
    asm("fma.rn.f32x2 %0, %1, %2, %3;" : "=l"(d) : "l"(a), "l"(b), "l"(c));
    return d;
}
__device__ __forceinline__ unsigned long long add2(
    unsigned long long a, unsigned long long b) {
    unsigned long long d;
    asm("add.rn.f32x2 %0, %1, %2;" : "=l"(d) : "l"(a), "l"(b));
    return d;
}
__device__ __forceinline__ unsigned long long mul2(
    unsigned long long a, unsigned long long b) {
    unsigned long long d;
    asm("mul.rn.f32x2 %0, %1, %2;" : "=l"(d) : "l"(a), "l"(b));
    return d;
}

union F4U { float4 f; unsigned long long u[2]; float s[4]; };

// ---------------------------------------------------------------------------
// Kernel 1: G = H @ W^T (8192x32x1024), d-packed FFMA2, writes G k-major.
// 128 threads / 32 rows. Thread: 4 rows x 2 k (k = tj, tj+16).
// Accumulators are u64 pairs over adjacent d (natural float4 halves) ->
// FFMA2 with zero packing overhead.
// ---------------------------------------------------------------------------
__global__ void __launch_bounds__(128) k1_proj(
    const float* __restrict__ H, const float* __restrict__ W)
{
    __shared__ float Hs[2][32][68];
    __shared__ float Ws[2][32][68];
    __shared__ float Gsm[32][33];   // staging for k-major writeout

    const int tid = threadIdx.x;
    const int r0  = blockIdx.x * 32;
    const int ti  = tid >> 4;       // 0..7
    const int tj  = tid & 15;       // k = tj, tj+16

    float4 hreg[4], wreg[4];

    #pragma unroll
    for (int p = 0; p < 4; p++) {
        const int e  = tid + p * 128;
        const int rr = e >> 4;
        const int cc = (e & 15) * 4;
        hreg[p] = *(const float4*)(H + (size_t)(r0 + rr) * DMODEL + cc);
        wreg[p] = *(const float4*)(W + (size_t)rr * DMODEL + cc);
    }
    #pragma unroll
    for (int p = 0; p < 4; p++) {
        const int e  = tid + p * 128;
        const int rr = e >> 4;
        const int cc = (e & 15) * 4;
        *(float4*)&Hs[0][rr][cc] = hreg[p];
        *(float4*)&Ws[0][rr][cc] = wreg[p];
    }
    __syncthreads();

    unsigned long long acc2[4][2];
    #pragma unroll
    for (int r = 0; r < 4; r++) { acc2[r][0] = 0ull; acc2[r][1] = 0ull; }

    for (int c = 0; c < 16; c++) {
        const int buf = c & 1;

        if (c < 15) {
            const int dc = (c + 1) * 64;
            #pragma unroll
            for (int p = 0; p < 4; p++) {
                const int e  = tid + p * 128;
                const int rr = e >> 4;
                const int cc = (e & 15) * 4;
                hreg[p] = *(const float4*)(H + (size_t)(r0 + rr) * DMODEL + dc + cc);
                wreg[p] = *(const float4*)(W + (size_t)rr * DMODEL + dc + cc);
            }
        }

        #pragma unroll
        for (int d4 = 0; d4 < 64; d4 += 4) {
            F4U gj0, gj1;
            gj0.f = *(const float4*)&Ws[buf][tj][d4];
            gj1.f = *(const float4*)&Ws[buf][tj + 16][d4];
            #pragma unroll
            for (int r = 0; r < 4; r++) {
                F4U gi;
                gi.f = *(const float4*)&Hs[buf][ti * 4 + r][d4];
                acc2[r][0] = fma2(gi.u[0], gj0.u[0], acc2[r][0]);
                acc2[r][0] = fma2(gi.u[1], gj0.u[1], acc2[r][0]);
                acc2[r][1] = fma2(gi.u[0], gj1.u[0], acc2[r][1]);
                acc2[r][1] = fma2(gi.u[1], gj1.u[1], acc2[r][1]);
            }
        }
        __syncthreads();

        if (c < 15) {
            #pragma unroll
            for (int p = 0; p < 4; p++) {
                const int e  = tid + p * 128;
                const int rr = e >> 4;
                const int cc = (e & 15) * 4;
                *(float4*)&Hs[buf ^ 1][rr][cc] = hreg[p];
                *(float4*)&Ws[buf ^ 1][rr][cc] = wreg[p];
            }
            __syncthreads();
        }
    }

    // Horizontal add of d-pairs, stage into Gsm, reduce norms.
    #pragma unroll
    for (int r = 0; r < 4; r++) {
        const int row = ti * 4 + r;
        float l0, h0, l1, h1;
        unpk2(acc2[r][0], l0, h0);
        unpk2(acc2[r][1], l1, h1);
        const float a0 = l0 + h0;
        const float a1 = l1 + h1;
        Gsm[row][tj]      = a0;
        Gsm[row][tj + 16] = a1;
        float sq = a0 * a0 + a1 * a1;
        sq += __shfl_xor_sync(0xffffffffu, sq, 1);
        sq += __shfl_xor_sync(0xffffffffu, sq, 2);
        sq += __shfl_xor_sync(0xffffffffu, sq, 4);
        sq += __shfl_xor_sync(0xffffffffu, sq, 8);
        if (tj == 0) g_Gsq[r0 + row] = sq;
    }
    __syncthreads();

    // k-major coalesced writeout: 128B consecutive per k.
    #pragma unroll
    for (int e = tid; e < 32 * 32; e += 128) {
        const int k = e >> 5;
        const int i = e & 31;
        g_Gt[(size_t)k * ROWS + r0 + i] = Gsm[i][k];
    }
}

// ---------------------------------------------------------------------------
// Kernel 2: 128x128 tile. Thread tile 8x8 in split chunks:
//   i in {ib..ib+3, ib+64..ib+67}, j in {jb..jb+3, jb+64..jb+67}
// (ib=ti*4, jb=tj*4) -> all LDS.128 wavefront-optimal, zero conflicts.
// Gram in i-pair-packed FFMA2. Fused packed epilogue with relu fold.
// ---------------------------------------------------------------------------
__global__ void __launch_bounds__(256, 2) k2_bias(
    const float* __restrict__ Bprev,
    const float* __restrict__ alpha_p,
    const float* __restrict__ beta_p,
    float* __restrict__ out)
{
    __shared__ float Gis[KDIM][128];
    __shared__ float Gjs[KDIM][128];
    __shared__ float sqi[128];
    __shared__ float sqj[128];

    const int b   = blockIdx.z;
    const int i0  = blockIdx.y * 128;
    const int j0  = blockIdx.x * 128;
    const int gi0 = b * NSEQ + i0;
    const int gj0 = b * NSEQ + j0;
    const int tid = threadIdx.x;

    const float alpha = *alpha_p;
    const float beta  = *beta_p;

    // Conflict-free loads: g_Gt is k-major, so smem rows are contiguous copies.
    #pragma unroll
    for (int e = tid; e < KDIM * 128; e += 256) {
        const int k = e >> 7;
        const int x = e & 127;
        Gis[k][x] = g_Gt[(size_t)k * ROWS + gi0 + x];
        Gjs[k][x] = g_Gt[(size_t)k * ROWS + gj0 + x];
    }
    if (tid < 128) {
        sqi[tid] = g_Gsq[gi0 + tid];
        sqj[tid] = g_Gsq[gj0 + tid];
    }
    __syncthreads();

    const int ti = tid >> 4;   // 0..15
    const int tj = tid & 15;   // 0..15
    const int ib = ti * 4;
    const int jb = tj * 4;

    // accp[p][jj]: p = i-pair (rows {ib,ib+1},{ib+2,ib+3},{ib+64,+65},{ib+66,+67})
    //              jj = 0..3 -> cols jb+jj ; jj = 4..7 -> cols jb+64+jj-4
    unsigned long long accp[4][8];
    #pragma unroll
    for (int p = 0; p < 4; p++)
        #pragma unroll
        for (int jj = 0; jj < 8; jj++)
            accp[p][jj] = 0ull;

    #pragma unroll 4
    for (int k = 0; k < KDIM; k++) {
        F4U gia, gic, gj0v, gj1v;
        gia.f  = *(const float4*)&Gis[k][ib];
        gic.f  = *(const float4*)&Gis[k][ib + 64];
        gj0v.f = *(const float4*)&Gjs[k][jb];
        gj1v.f = *(const float4*)&Gjs[k][jb + 64];

        unsigned long long gjb[8];
        #pragma unroll
        for (int jj = 0; jj < 4; jj++) {
            gjb[jj]     = pk2(gj0v.s[jj], gj0v.s[jj]);
            gjb[jj + 4] = pk2(gj1v.s[jj], gj1v.s[jj]);
        }

        #pragma unroll
        for (int jj = 0; jj < 8; jj++) {
            accp[0][jj] = fma2(gia.u[0], gjb[jj], accp[0][jj]);
            accp[1][jj] = fma2(gia.u[1], gjb[jj], accp[1][jj]);
            accp[2][jj] = fma2(gic.u[0], gjb[jj], accp[2][jj]);
            accp[3][jj] = fma2(gic.u[1], gjb[jj], accp[3][jj]);
        }
    }

    // Epilogue: raw = si + sj - 2*acc; ab = alpha*b;
    // result = clamp(min(ab, fma(-beta, raw, ab)), -10, 10)
    const unsigned long long alpha2   = pk2(alpha, alpha);
    const unsigned long long negbeta2 = pk2(-beta, -beta);
    const unsigned long long negtwo2  = pk2(-2.0f, -2.0f);

    unsigned long long sj2[8];
    #pragma unroll
    for (int jj = 0; jj < 4; jj++) {
        float s0 = sqj[jb + jj];
        float s1 = sqj[jb + 64 + jj];
        sj2[jj]     = pk2(s0, s0);
        sj2[jj + 4] = pk2(s1, s1);
    }

    const int prow[4] = {ib, ib + 2, ib + 64, ib + 66};

    #pragma unroll
    for (int p = 0; p < 4; p++) {
        const int rl = prow[p];
        const unsigned long long si2 = pk2(sqi[rl], sqi[rl + 1]);
        const size_t rb0 = ((size_t)b * NSEQ + (i0 + rl)) * NSEQ + j0;
        const size_t rb1 = rb0 + NSEQ;

        #pragma unroll
        for (int jc = 0; jc < 2; jc++) {
            const int coff = jb + jc * 64;
            F4U bvl, bvh;
            bvl.f = *(const float4*)(Bprev + rb0 + coff);
            bvh.f = *(const float4*)(Bprev + rb1 + coff);

            F4U rlo, rhi;
            #pragma unroll
            for (int jj = 0; jj < 4; jj++) {
                const int idx = jc * 4 + jj;
                const unsigned long long sij2 = add2(si2, sj2[idx]);
                const unsigned long long raw2 = fma2(negtwo2, accp[p][idx], sij2);
                const unsigned long long bp2  = pk2(bvl.s[jj], bvh.s[jj]);
                const unsigned long long ab2  = mul2(alpha2, bp2);
                const unsigned long long t2   = fma2(negbeta2, raw2, ab2);
                float abl, abh, tl, th;
                unpk2(ab2, abl, abh);
                unpk2(t2, tl, th);
                rlo.s[jj] = fminf(fmaxf(fminf(abl, tl), -CLAMP_V), CLAMP_V);
                rhi.s[jj] = fminf(fmaxf(fminf(abh, th), -CLAMP_V), CLAMP_V);
            }
            *(float4*)(out + rb0 + coff) = rlo.f;
            *(float4*)(out + rb1 + coff) = rhi.f;
        }
    }
}

// ---------------------------------------------------------------------------
extern "C" void kernel_launch(void* const* d_in, const int* in_sizes, int n_in,
                              void* d_out, int out_size)
{
    const float* H     = (const float*)d_in[0];
    const float* Bprev = (const float*)d_in[1];
    const float* W     = (const float*)d_in[2];
    const float* alpha = (const float*)d_in[3];
    const float* beta  = (const float*)d_in[4];
    float* out = (float*)d_out;

    k1_proj<<<ROWS / 32, 128>>>(H, W);

    dim3 g2(NSEQ / 128, NSEQ / 128, BATCH);
    k2_bias<<<g2, 256>>>(Bprev, alpha, beta, out);
}

// round 4
// speedup vs baseline: 1.5800x; 1.5800x over previous
#include <cuda_runtime.h>
#include <cstdint>

#define BATCH   4
#define NSEQ    2048
#define DMODEL  1024
#define KDIM    32
#define ROWS    (BATCH * NSEQ)
#define CLAMP_V 10.0f

// Scratch: G stored K-MAJOR (g_Gt[k][row]) + per-row squared norms.
__device__ float g_Gt[(size_t)KDIM * ROWS];
__device__ float g_Gsq[ROWS];

// ---- packed f32x2 helpers ---------------------------------------------------
__device__ __forceinline__ unsigned long long pk2(float a, float b) {
    unsigned long long r;
    asm("mov.b64 %0, {%1, %2};" : "=l"(r) : "f"(a), "f"(b));
    return r;
}
__device__ __forceinline__ void unpk2(unsigned long long v, float& a, float& b) {
    asm("mov.b64 {%0, %1}, %2;" : "=f"(a), "=f"(b) : "l"(v));
}
__device__ __forceinline__ unsigned long long fma2(
    unsigned long long a, unsigned long long b, unsigned long long c) {
    unsigned long long d;
    asm("fma.rn.f32x2 %0, %1, %2, %3;" : "=l"(d) : "l"(a), "l"(b), "l"(c));
    return d;
}
__device__ __forceinline__ unsigned long long add2(
    unsigned long long a, unsigned long long b) {
    unsigned long long d;
    asm("add.rn.f32x2 %0, %1, %2;" : "=l"(d) : "l"(a), "l"(b));
    return d;
}
__device__ __forceinline__ unsigned long long mul2(
    unsigned long long a, unsigned long long b) {
    unsigned long long d;
    asm("mul.rn.f32x2 %0, %1, %2;" : "=l"(d) : "l"(a), "l"(b));
    return d;
}

union F4U { float4 f; unsigned long long u[2]; float s[4]; };

// ---------------------------------------------------------------------------
// Kernel 1: G = H @ W^T (8192x32x1024) + row norms, G written k-major.
// 256 threads / 32 rows. Thread tile: 2 rows (ti*2..+1) x 2 k (tj, tj+16).
// Scalar FFMA hot loop (known-good R2 pattern), register double-buffering.
// ---------------------------------------------------------------------------
__global__ void __launch_bounds__(256) k1_proj(
    const float* __restrict__ H, const float* __restrict__ W)
{
    __shared__ float Hs[2][32][68];
    __shared__ float Ws[2][32][68];
    __shared__ float Gsm[32][33];

    const int tid = threadIdx.x;
    const int r0  = blockIdx.x * 32;
    const int ti  = tid >> 4;       // 0..15 -> rows ti*2, ti*2+1
    const int tj  = tid & 15;       // k = tj, tj+16

    float4 hreg[2], wreg[2];

    // Prologue: chunk 0 (32 rows x 64 d = 512 float4 per array, 2/thread)
    #pragma unroll
    for (int p = 0; p < 2; p++) {
        const int e  = tid + p * 256;
        const int rr = e >> 4;
        const int cc = (e & 15) * 4;
        hreg[p] = *(const float4*)(H + (size_t)(r0 + rr) * DMODEL + cc);
        wreg[p] = *(const float4*)(W + (size_t)rr * DMODEL + cc);
    }
    #pragma unroll
    for (int p = 0; p < 2; p++) {
        const int e  = tid + p * 256;
        const int rr = e >> 4;
        const int cc = (e & 15) * 4;
        *(float4*)&Hs[0][rr][cc] = hreg[p];
        *(float4*)&Ws[0][rr][cc] = wreg[p];
    }
    __syncthreads();

    float acc[2][2] = {{0.f, 0.f}, {0.f, 0.f}};

    for (int c = 0; c < 16; c++) {
        const int buf = c & 1;

        if (c < 15) {
            const int dc = (c + 1) * 64;
            #pragma unroll
            for (int p = 0; p < 2; p++) {
                const int e  = tid + p * 256;
                const int rr = e >> 4;
                const int cc = (e & 15) * 4;
                hreg[p] = *(const float4*)(H + (size_t)(r0 + rr) * DMODEL + dc + cc);
                wreg[p] = *(const float4*)(W + (size_t)rr * DMODEL + dc + cc);
            }
        }

        #pragma unroll
        for (int d4 = 0; d4 < 64; d4 += 4) {
            const float4 w0 = *(const float4*)&Ws[buf][tj][d4];
            const float4 w1 = *(const float4*)&Ws[buf][tj + 16][d4];
            #pragma unroll
            for (int r = 0; r < 2; r++) {
                const float4 h = *(const float4*)&Hs[buf][ti * 2 + r][d4];
                acc[r][0] += h.x * w0.x; acc[r][0] += h.y * w0.y;
                acc[r][0] += h.z * w0.z; acc[r][0] += h.w * w0.w;
                acc[r][1] += h.x * w1.x; acc[r][1] += h.y * w1.y;
                acc[r][1] += h.z * w1.z; acc[r][1] += h.w * w1.w;
            }
        }
        __syncthreads();

        if (c < 15) {
            #pragma unroll
            for (int p = 0; p < 2; p++) {
                const int e  = tid + p * 256;
                const int rr = e >> 4;
                const int cc = (e & 15) * 4;
                *(float4*)&Hs[buf ^ 1][rr][cc] = hreg[p];
                *(float4*)&Ws[buf ^ 1][rr][cc] = wreg[p];
            }
            __syncthreads();
        }
    }

    // Stage + row-norm reduce (16 tj lanes per row, within half-warp).
    #pragma unroll
    for (int r = 0; r < 2; r++) {
        const int row = ti * 2 + r;
        const float a0 = acc[r][0];
        const float a1 = acc[r][1];
        Gsm[row][tj]      = a0;
        Gsm[row][tj + 16] = a1;
        float sq = a0 * a0 + a1 * a1;
        sq += __shfl_xor_sync(0xffffffffu, sq, 1);
        sq += __shfl_xor_sync(0xffffffffu, sq, 2);
        sq += __shfl_xor_sync(0xffffffffu, sq, 4);
        sq += __shfl_xor_sync(0xffffffffu, sq, 8);
        if (tj == 0) g_Gsq[r0 + row] = sq;
    }
    __syncthreads();

    // k-major coalesced writeout (128B contiguous per warp).
    #pragma unroll
    for (int e = tid; e < 32 * 32; e += 256) {
        const int k = e >> 5;
        const int i = e & 31;
        g_Gt[(size_t)k * ROWS + r0 + i] = Gsm[i][k];
    }
}

// ---------------------------------------------------------------------------
// Kernel 2: 128(i) x 64(j) tile (R2 shape). Gram in i-pair-packed FFMA2.
// Coalesced float4 tile loads from k-major G. 4 blocks/SM target.
// ---------------------------------------------------------------------------
__global__ void __launch_bounds__(256, 4) k2_bias(
    const float* __restrict__ Bprev,
    const float* __restrict__ alpha_p,
    const float* __restrict__ beta_p,
    float* __restrict__ out)
{
    __shared__ float Gis[KDIM][128];
    __shared__ float Gjs[KDIM][64];
    __shared__ float sqi[128];
    __shared__ float sqj[64];

    const int b   = blockIdx.z;
    const int i0  = blockIdx.y * 128;
    const int j0  = blockIdx.x * 64;
    const int gi0 = b * NSEQ + i0;
    const int gj0 = b * NSEQ + j0;
    const int tid = threadIdx.x;

    const float alpha = *alpha_p;
    const float beta  = *beta_p;

    // Coalesced float4 fills (g_Gt is k-major).
    #pragma unroll
    for (int e = tid; e < KDIM * 32; e += 256) {        // 1024 float4 for Gis
        const int k = e >> 5;
        const int x = (e & 31) * 4;
        *(float4*)&Gis[k][x] = *(const float4*)(g_Gt + (size_t)k * ROWS + gi0 + x);
    }
    #pragma unroll
    for (int e = tid; e < KDIM * 16; e += 256) {        // 512 float4 for Gjs
        const int k = e >> 4;
        const int x = (e & 15) * 4;
        *(float4*)&Gjs[k][x] = *(const float4*)(g_Gt + (size_t)k * ROWS + gj0 + x);
    }
    if (tid < 128) sqi[tid] = g_Gsq[gi0 + tid];
    if (tid < 64)  sqj[tid] = g_Gsq[gj0 + tid];
    __syncthreads();

    const int ti = tid >> 4;    // 0..15
    const int tj = tid & 15;    // 0..15
    const int ib = ti * 8;
    const int jb = tj * 4;

    // accp[ip][jj]: rows (ib+2ip, ib+2ip+1) x col jb+jj, packed over the i-pair.
    unsigned long long accp[4][4];
    #pragma unroll
    for (int ip = 0; ip < 4; ip++)
        #pragma unroll
        for (int jj = 0; jj < 4; jj++)
            accp[ip][jj] = 0ull;

    #pragma unroll 8
    for (int k = 0; k < KDIM; k++) {
        F4U gia, gib;
        gia.f = *(const float4*)&Gis[k][ib];
        gib.f = *(const float4*)&Gis[k][ib + 4];
        const float4 gj = *(const float4*)&Gjs[k][jb];
        const unsigned long long g0 = pk2(gj.x, gj.x);
        const unsigned long long g1 = pk2(gj.y, gj.y);
        const unsigned long long g2 = pk2(gj.z, gj.z);
        const unsigned long long g3 = pk2(gj.w, gj.w);

        accp[0][0] = fma2(gia.u[0], g0, accp[0][0]);
        accp[0][1] = fma2(gia.u[0], g1, accp[0][1]);
        accp[0][2] = fma2(gia.u[0], g2, accp[0][2]);
        accp[0][3] = fma2(gia.u[0], g3, accp[0][3]);
        accp[1][0] = fma2(gia.u[1], g0, accp[1][0]);
        accp[1][1] = fma2(gia.u[1], g1, accp[1][1]);
        accp[1][2] = fma2(gia.u[1], g2, accp[1][2]);
        accp[1][3] = fma2(gia.u[1], g3, accp[1][3]);
        accp[2][0] = fma2(gib.u[0], g0, accp[2][0]);
        accp[2][1] = fma2(gib.u[0], g1, accp[2][1]);
        accp[2][2] = fma2(gib.u[0], g2, accp[2][2]);
        accp[2][3] = fma2(gib.u[0], g3, accp[2][3]);
        accp[3][0] = fma2(gib.u[1], g0, accp[3][0]);
        accp[3][1] = fma2(gib.u[1], g1, accp[3][1]);
        accp[3][2] = fma2(gib.u[1], g2, accp[3][2]);
        accp[3][3] = fma2(gib.u[1], g3, accp[3][3]);
    }

    // Epilogue: raw = si + sj - 2*acc; ab = alpha*b;
    // result = clamp(min(ab, fma(-beta, raw, ab)), -10, 10).
    const unsigned long long alpha2   = pk2(alpha, alpha);
    const unsigned long long negbeta2 = pk2(-beta, -beta);
    const unsigned long long negtwo2  = pk2(-2.0f, -2.0f);

    unsigned long long sj2[4];
    #pragma unroll
    for (int jj = 0; jj < 4; jj++) {
        const float s = sqj[jb + jj];
        sj2[jj] = pk2(s, s);
    }

    const size_t base = ((size_t)b * NSEQ + (i0 + ib)) * NSEQ + (j0 + jb);

    #pragma unroll
    for (int ip = 0; ip < 4; ip++) {
        const int rl = 2 * ip;
        const unsigned long long si2 = pk2(sqi[ib + rl], sqi[ib + rl + 1]);

        F4U bvl, bvh;
        bvl.f = __ldcs((const float4*)(Bprev + base + (size_t)rl * NSEQ));
        bvh.f = __ldcs((const float4*)(Bprev + base + (size_t)(rl + 1) * NSEQ));

        F4U rlo, rhi;
        #pragma unroll
        for (int jj = 0; jj < 4; jj++) {
            const unsigned long long sij2 = add2(si2, sj2[jj]);
            const unsigned long long raw2 = fma2(negtwo2, accp[ip][jj], sij2);
            const unsigned long long bp2  = pk2(bvl.s[jj], bvh.s[jj]);
            const unsigned long long ab2  = mul2(alpha2, bp2);
            const unsigned long long t2   = fma2(negbeta2, raw2, ab2);
            float abl, abh, tl, th;
            unpk2(ab2, abl, abh);
            unpk2(t2, tl, th);
            rlo.s[jj] = fminf(fmaxf(fminf(abl, tl), -CLAMP_V), CLAMP_V);
            rhi.s[jj] = fminf(fmaxf(fminf(abh, th), -CLAMP_V), CLAMP_V);
        }
        __stcs((float4*)(out + base + (size_t)rl * NSEQ), rlo.f);
        __stcs((float4*)(out + base + (size_t)(rl + 1) * NSEQ), rhi.f);
    }
}

// ---------------------------------------------------------------------------
extern "C" void kernel_launch(void* const* d_in, const int* in_sizes, int n_in,
                              void* d_out, int out_size)
{
    const float* H     = (const float*)d_in[0];
    const float* Bprev = (const float*)d_in[1];
    const float* W     = (const float*)d_in[2];
    const float* alpha = (const float*)d_in[3];
    const float* beta  = (const float*)d_in[4];
    float* out = (float*)d_out;

    k1_proj<<<ROWS / 32, 256>>>(H, W);

    dim3 g2(NSEQ / 64, NSEQ / 128, BATCH);
    k2_bias<<<g2, 256>>>(Bprev, alpha, beta, out);
}